// round 15
// baseline (speedup 1.0000x reference)
#include <cuda_runtime.h>
#include <cuda_fp16.h>
#include <cstdint>

#define HEADS 8
#define SEQ   4096
#define DQK   96
#define DV    64
#define ATTN_SCALE 0.17677669529663689f   // (256/8)^-0.5
#define P_SCALE 0.015625f                 // 2^-6 (overflow guard for fp16 P)
#define NSPLIT 4

// ---------------- scratch (device globals: no allocation allowed) ----------
__device__ __half Qg[(size_t)HEADS * SEQ * DQK];   // [h][n][96] fp16, pre-scaled
__device__ __half Kg[(size_t)HEADS * SEQ * DQK];   // [h][n][96] fp16
__device__ __half Vtg[(size_t)HEADS * DV * SEQ];   // [h*64+d][n] fp16 (transposed V)
__device__ __half Ah[(size_t)SEQ * 768];           // qk fp16 row-major
__device__ __half Ch[(size_t)SEQ * 512];           // v_cls fp16 row-major
__device__ __half Wqt[(size_t)1536 * 768];         // W_qk^T fp16 [n][k]
__device__ __half Wvt[(size_t)512 * 512];          // W_v^T  fp16 [n][k]
__device__ __half Mh[(size_t)SEQ * SEQ];           // masks fp16
__device__ float  Op[(size_t)NSPLIT * SEQ * 512];  // split partial O (P_SCALE applied)
__device__ float  Zp[NSPLIT * HEADS * SEQ];        // split partial exp-sums
__device__ float  Wsp[NSPLIT * HEADS * SEQ];       // split partial mask row-sums

// ---------------- helpers --------------------------------------------------
__device__ __forceinline__ void cp16(uint32_t dst_smem, const void* src) {
    asm volatile("cp.async.cg.shared.global [%0], [%1], 16;" :: "r"(dst_smem), "l"(src));
}
#define CP_COMMIT() asm volatile("cp.async.commit_group;" ::)
#define CP_WAIT1()  asm volatile("cp.async.wait_group 1;" ::)
#define CP_WAIT0()  asm volatile("cp.async.wait_group 0;" ::)

__device__ __forceinline__ uint32_t s2u(const void* p) {
    return (uint32_t)__cvta_generic_to_shared(p);
}

// fp16: D(16x8,f32) += A(16x16,f16) * B(16x8,f16)
__device__ __forceinline__ void mma16(float c[4],
                                      uint32_t a0, uint32_t a1, uint32_t a2, uint32_t a3,
                                      uint32_t b0, uint32_t b1) {
    asm volatile(
        "mma.sync.aligned.m16n8k16.row.col.f32.f16.f16.f32 "
        "{%0,%1,%2,%3}, {%4,%5,%6,%7}, {%8,%9}, {%0,%1,%2,%3};"
        : "+f"(c[0]), "+f"(c[1]), "+f"(c[2]), "+f"(c[3])
        : "r"(a0), "r"(a1), "r"(a2), "r"(a3), "r"(b0), "r"(b1));
}

// ldmatrix x4: four 8x8 b16 matrices; lanes 0-7/8-15/16-23/24-31 supply rows
__device__ __forceinline__ void ldsm4(uint32_t& x0, uint32_t& x1, uint32_t& x2, uint32_t& x3,
                                      uint32_t addr) {
    asm volatile("ldmatrix.sync.aligned.m8n8.x4.shared.b16 {%0,%1,%2,%3}, [%4];"
                 : "=r"(x0), "=r"(x1), "=r"(x2), "=r"(x3) : "r"(addr));
}

__device__ __forceinline__ uint32_t pack_h2(float lo, float hi) {
    __half2 h = __floats2half2_rn(lo, hi);
    return *reinterpret_cast<uint32_t*>(&h);
}

// ---------------- input conversion kernels ---------------------------------
__global__ __launch_bounds__(256) void cvt_inputs(const float* __restrict__ qk,
                                                  const float* __restrict__ v_cls) {
    const int i = blockIdx.x * 256 + threadIdx.x;          // float4 index
    if (i < (SEQ * 768) / 4) {
        float4 v = __ldg(reinterpret_cast<const float4*>(qk) + i);
        uint32_t* o = reinterpret_cast<uint32_t*>(Ah);
        o[i * 2]     = pack_h2(v.x, v.y);
        o[i * 2 + 1] = pack_h2(v.z, v.w);
    }
    if (i < (SEQ * 512) / 4) {
        float4 v = __ldg(reinterpret_cast<const float4*>(v_cls) + i);
        uint32_t* o = reinterpret_cast<uint32_t*>(Ch);
        o[i * 2]     = pack_h2(v.x, v.y);
        o[i * 2 + 1] = pack_h2(v.z, v.w);
    }
}

// masks f32 -> fp16 (8 floats / thread)
__global__ __launch_bounds__(256) void cvt_mask(const float* __restrict__ m) {
    const size_t i = (size_t)blockIdx.x * 256 + threadIdx.x;   // uint4 index
    const float4 a = __ldg(reinterpret_cast<const float4*>(m) + 2 * i);
    const float4 b = __ldg(reinterpret_cast<const float4*>(m) + 2 * i + 1);
    uint4 r;
    r.x = pack_h2(a.x, a.y); r.y = pack_h2(a.z, a.w);
    r.z = pack_h2(b.x, b.y); r.w = pack_h2(b.z, b.w);
    reinterpret_cast<uint4*>(Mh)[i] = r;
}

// W [K][N] f32 -> W^T [N][K] fp16, smem-tiled 32x32 transpose
__global__ __launch_bounds__(256) void tr_cvt(const float* __restrict__ in,
                                              int K, int N, int which) {
    __shared__ float tile[32][33];
    __half* out = which ? Wvt : Wqt;
    const int n0 = blockIdx.x * 32, k0 = blockIdx.y * 32;
    const int tx = threadIdx.x & 31, ty = threadIdx.x >> 5;   // 32 x 8
#pragma unroll
    for (int i = 0; i < 32; i += 8)
        tile[ty + i][tx] = __ldg(&in[(size_t)(k0 + ty + i) * N + n0 + tx]);
    __syncthreads();
#pragma unroll
    for (int i = 0; i < 32; i += 8)
        out[(size_t)(n0 + ty + i) * K + k0 + tx] = __float2half_rn(tile[tx][ty + i]);
}

// ---------------- fp16 projection GEMM (ldmatrix operands) -----------------
#define FA_STRIDE 20
#define FW_STRIDE 20
#define FSTAGE    (128 * FA_STRIDE + 64 * FW_STRIDE)   // 3840 words
#define PROJ_SMEM (2 * FSTAGE * 4)

__global__ __launch_bounds__(128) void proj_kernel() {
    extern __shared__ uint32_t smw[];

    const int  tid  = threadIdx.x;
    const int  w    = tid >> 5;
    const int  lane = tid & 31;
    const bool isV  = blockIdx.x >= 24;
    const uint32_t* A  = reinterpret_cast<const uint32_t*>(isV ? Ch : Ah);
    const uint32_t* Wt = reinterpret_cast<const uint32_t*>(isV ? Wvt : Wqt);
    const int  Kw   = isV ? 256 : 384;     // words (half2) per row
    const int  T    = isV ? 16 : 24;       // k-tiles of 32 halves
    const int  n0   = (isV ? (blockIdx.x - 24) : blockIdx.x) * 64;
    const int  m0   = blockIdx.y * 128;
    const uint32_t smem0 = s2u(smw);

    // ldmatrix per-lane address components
    const int r_loc = lane & 7;
    const uint32_t afrag = (uint32_t)((r_loc + ((lane >> 3) & 1) * 8) * FA_STRIDE
                                      + ((lane >> 4) & 1) * 4) * 4u;
    const uint32_t bfrag = (uint32_t)(((((lane >> 4) & 1) * 8 + r_loc) * FW_STRIDE)
                                      + ((lane >> 3) & 1) * 4) * 4u;

    float acc[2][8][4];
#pragma unroll
    for (int r2 = 0; r2 < 2; r2++)
#pragma unroll
        for (int i = 0; i < 8; i++)
#pragma unroll
            for (int j = 0; j < 4; j++) acc[r2][i][j] = 0.f;

    auto issue = [&](int buf, int itk) {
        uint32_t Ab = smem0 + (uint32_t)(buf * FSTAGE) * 4u;
        uint32_t Wb = Ab + 128 * FA_STRIDE * 4u;
#pragma unroll
        for (int j = 0; j < 4; j++) {         // A tile: 128 rows x 16 words
            int idx = tid + j * 128;
            int r = idx >> 2, c = idx & 3;
            cp16(Ab + (uint32_t)(r * FA_STRIDE + c * 4) * 4u,
                 A + (size_t)(m0 + r) * Kw + itk * 16 + c * 4);
        }
#pragma unroll
        for (int j = 0; j < 2; j++) {         // W tile: 64 rows x 16 words
            int idx = tid + j * 128;
            int r = idx >> 2, c = idx & 3;
            cp16(Wb + (uint32_t)(r * FW_STRIDE + c * 4) * 4u,
                 Wt + (size_t)(n0 + r) * Kw + itk * 16 + c * 4);
        }
    };

    issue(0, 0); CP_COMMIT();

    for (int it = 0; it < T; it++) {
        if (it + 1 < T) { issue((it + 1) & 1, it + 1); CP_COMMIT(); CP_WAIT1(); }
        else            { CP_WAIT0(); }
        __syncthreads();

        const uint32_t Ab = smem0 + (uint32_t)((it & 1) * FSTAGE) * 4u;
        const uint32_t Wb = Ab + 128 * FA_STRIDE * 4u;

#pragma unroll
        for (int ks = 0; ks < 2; ks++) {
            uint32_t a[2][4];
#pragma unroll
            for (int r2 = 0; r2 < 2; r2++)
                ldsm4(a[r2][0], a[r2][1], a[r2][2], a[r2][3],
                      Ab + afrag + (uint32_t)(((w * 32 + r2 * 16) * FA_STRIDE + ks * 8)) * 4u);
#pragma unroll
            for (int nfp = 0; nfp < 4; nfp++) {
                uint32_t b0, b1, b2, b3;
                ldsm4(b0, b1, b2, b3,
                      Wb + bfrag + (uint32_t)((nfp * 2) * 8 * FW_STRIDE + ks * 8) * 4u);
                mma16(acc[0][nfp * 2],     a[0][0], a[0][1], a[0][2], a[0][3], b0, b1);
                mma16(acc[1][nfp * 2],     a[1][0], a[1][1], a[1][2], a[1][3], b0, b1);
                mma16(acc[0][nfp * 2 + 1], a[0][0], a[0][1], a[0][2], a[0][3], b2, b3);
                mma16(acc[1][nfp * 2 + 1], a[1][0], a[1][1], a[1][2], a[1][3], b2, b3);
            }
        }
        __syncthreads();
    }

    // epilogue -> fp16 scratch
    const int g = lane >> 2;
    const int t = lane & 3;
#pragma unroll
    for (int r2 = 0; r2 < 2; r2++)
#pragma unroll
        for (int nf = 0; nf < 8; nf++) {
            const int row = m0 + w * 32 + r2 * 16 + g;
            const int col = n0 + nf * 8 + 2 * t;
            if (!isV) {
                const bool isQ = col < 768;
                const int cc = isQ ? col : col - 768;
                const int h = cc / 96, d = cc - h * 96;
                const float sc = isQ ? ATTN_SCALE : 1.f;
                uint32_t* dst = reinterpret_cast<uint32_t*>(isQ ? Qg : Kg);
                dst[(((size_t)h * SEQ + row) * DQK + d) >> 1] =
                    pack_h2(acc[r2][nf][0] * sc, acc[r2][nf][1] * sc);
                dst[(((size_t)h * SEQ + row + 8) * DQK + d) >> 1] =
                    pack_h2(acc[r2][nf][2] * sc, acc[r2][nf][3] * sc);
            } else {
                Vtg[(size_t)col * SEQ + row]           = __float2half_rn(acc[r2][nf][0]);
                Vtg[(size_t)(col + 1) * SEQ + row]     = __float2half_rn(acc[r2][nf][1]);
                Vtg[(size_t)col * SEQ + row + 8]       = __float2half_rn(acc[r2][nf][2]);
                Vtg[(size_t)(col + 1) * SEQ + row + 8] = __float2half_rn(acc[r2][nf][3]);
            }
        }
}

// ---------------- fp16 flash attention: 64-row CTA, 4 CTAs/SM --------------
// CTA = 64 q-rows x 1 head x quarter-keys; warp = 16 rows (no M-block — with
// ldmatrix the issues/mma stays ~2.6, and 4 CTAs/SM gives 4 warps/SMSP).
// Bc=64; 2 chunks of 32 keys; register-P; ldmatrix B; fp16 mask prefetch.
#define BC 64
#define KW0 0
#define KW1 3328
#define VW0 6656
#define VW1 8960
#define ATTN_SMEM (11264 * 4)    // 45056 B -> 4 CTAs/SM (180224 <= 227KB)

__global__ __launch_bounds__(128, 4) void attn_kernel() {
    extern __shared__ uint32_t smw[];

    const int tid   = threadIdx.x;
    const int w     = tid >> 5;
    const int lane  = tid & 31;
    const int g     = lane >> 2;
    const int t     = lane & 3;
    const int h     = blockIdx.x;
    const int q0    = blockIdx.y * 64;
    const int split = blockIdx.z;
    const int kt0   = split * (SEQ / NSPLIT);
    const int rb    = q0 + w * 16;          // warp's first q-row
    const uint32_t smem0 = s2u(smw);

    const __half* Kh = &Kg[(size_t)h * SEQ * DQK];
    const __half* Vh = &Vtg[(size_t)h * DV * SEQ];
    const uint32_t* Qw = reinterpret_cast<const uint32_t*>(&Qg[(size_t)h * SEQ * DQK]);
    const uint32_t* Mw = reinterpret_cast<const uint32_t*>(Mh);

    // ldmatrix per-lane address components (B operands)
    const int r_loc = lane & 7;
    const uint32_t kfrag = (uint32_t)((((lane >> 4) & 1) * 8 + r_loc) * 52
                                      + ((lane >> 3) & 1) * 4) * 4u;
    const uint32_t vfrag = (uint32_t)((((lane >> 4) & 1) * 8 + r_loc) * 36
                                      + ((lane >> 3) & 1) * 4) * 4u;

    // Q A-fragments (row stride 48 words)
    uint32_t qa[6][4];
#pragma unroll
    for (int ks = 0; ks < 6; ks++) {
        qa[ks][0] = __ldg(&Qw[(size_t)(rb + g) * 48 + ks * 8 + t]);
        qa[ks][1] = __ldg(&Qw[(size_t)(rb + 8 + g) * 48 + ks * 8 + t]);
        qa[ks][2] = __ldg(&Qw[(size_t)(rb + g) * 48 + ks * 8 + t + 4]);
        qa[ks][3] = __ldg(&Qw[(size_t)(rb + 8 + g) * 48 + ks * 8 + t + 4]);
    }

    // mask word row bases (fp16, word = 2 cols)
    const size_t mrow0 = (size_t)(rb + g) * (SEQ / 2) + t;
    const size_t mrow1 = (size_t)(rb + 8 + g) * (SEQ / 2) + t;

    float o[8][4];
#pragma unroll
    for (int i = 0; i < 8; i++)
#pragma unroll
        for (int j = 0; j < 4; j++) o[i][j] = 0.f;

    float zz0 = 0.f, zz1 = 0.f;
    float ws0 = 0.f, ws1 = 0.f;

    auto issue = [&](int buf, int kt) {
        uint32_t Kb = smem0 + (buf ? KW1 : KW0) * 4u;
        uint32_t Vb = smem0 + (buf ? VW1 : VW0) * 4u;
#pragma unroll
        for (int j = 0; j < 6; j++) {
            int idx = tid + j * 128;
            int r = idx / 12, c = idx % 12;
            cp16(Kb + (uint32_t)(r * 52 + c * 4) * 4u, Kh + (size_t)(kt + r) * DQK + c * 8);
        }
#pragma unroll
        for (int j = 0; j < 4; j++) {
            int idx = tid + j * 128;
            int d0 = idx >> 3, c = idx & 7;
            cp16(Vb + (uint32_t)(d0 * 36 + c * 4) * 4u, Vh + (size_t)d0 * SEQ + kt + c * 8);
        }
    };

    issue(0, kt0); CP_COMMIT();

#pragma unroll 1
    for (int it = 0; it < SEQ / (NSPLIT * BC); it++) {
        const int kt  = kt0 + it * BC;
        const int buf = it & 1;

        CP_WAIT0();
        __syncthreads();
        if (it + 1 < SEQ / (NSPLIT * BC)) { issue(buf ^ 1, kt + BC); CP_COMMIT(); }

        const uint32_t Kb = smem0 + (buf ? KW1 : KW0) * 4u;
        const uint32_t Vb = smem0 + (buf ? VW1 : VW0) * 4u;
        const int ktw = kt >> 1;   // mask word col base

#pragma unroll
        for (int c2 = 0; c2 < 2; c2++) {
            // ---- prefetch this chunk's fp16 mask words (hidden under S-mma) ----
            uint32_t mk0[4], mk1[4];
#pragma unroll
            for (int nfl = 0; nfl < 4; nfl++) {
                const int nf = c2 * 4 + nfl;
                mk0[nfl] = __ldg(&Mw[mrow0 + ktw + nf * 4]);
                mk1[nfl] = __ldg(&Mw[mrow1 + ktw + nf * 4]);
            }

            // ---- S = Q K^T for this 32-key chunk (ldmatrix B) ----
            float s[4][4];
#pragma unroll
            for (int i = 0; i < 4; i++)
#pragma unroll
                for (int j = 0; j < 4; j++) s[i][j] = 0.f;
#pragma unroll
            for (int ks = 0; ks < 6; ks++) {
#pragma unroll
                for (int nfp = 0; nfp < 2; nfp++) {
                    uint32_t b0, b1, b2, b3;
                    ldsm4(b0, b1, b2, b3,
                          Kb + kfrag + (uint32_t)((c2 * 4 + nfp * 2) * 416 + ks * 8) * 4u);
                    mma16(s[nfp * 2],     qa[ks][0], qa[ks][1], qa[ks][2], qa[ks][3], b0, b1);
                    mma16(s[nfp * 2 + 1], qa[ks][0], qa[ks][1], qa[ks][2], qa[ks][3], b2, b3);
                }
            }

            // ---- softmax numerator * mask -> packed PV A-fragments ----
            uint32_t pa[2][4];   // [kql][a0..a3]
#pragma unroll
            for (int nfl = 0; nfl < 4; nfl++) {
                float2 mv0 = __half22float2(*reinterpret_cast<__half2*>(&mk0[nfl]));
                float2 mv1 = __half22float2(*reinterpret_cast<__half2*>(&mk1[nfl]));
                float e00 = __expf(s[nfl][0]);
                float e01 = __expf(s[nfl][1]);
                float e10 = __expf(s[nfl][2]);
                float e11 = __expf(s[nfl][3]);
                zz0 += e00 + e01;  zz1 += e10 + e11;
                ws0 += mv0.x + mv0.y;  ws1 += mv1.x + mv1.y;
                pa[nfl >> 1][(nfl & 1) * 2 + 0] =
                    pack_h2(e00 * mv0.x * P_SCALE, e01 * mv0.y * P_SCALE);
                pa[nfl >> 1][(nfl & 1) * 2 + 1] =
                    pack_h2(e10 * mv1.x * P_SCALE, e11 * mv1.y * P_SCALE);
            }

            // ---- O += P~ @ V (ldmatrix B) ----
#pragma unroll
            for (int kql = 0; kql < 2; kql++) {
                const int kq = c2 * 2 + kql;
#pragma unroll
                for (int nfp = 0; nfp < 4; nfp++) {
                    uint32_t b0, b1, b2, b3;
                    ldsm4(b0, b1, b2, b3,
                          Vb + vfrag + (uint32_t)((nfp * 2) * 288 + kq * 8) * 4u);
                    mma16(o[nfp * 2],     pa[kql][0], pa[kql][1], pa[kql][2], pa[kql][3], b0, b1);
                    mma16(o[nfp * 2 + 1], pa[kql][0], pa[kql][1], pa[kql][2], pa[kql][3], b2, b3);
                }
            }
        }
    }

    // ---- epilogue: quad-reduce z/ws, write partials ----
    zz0 += __shfl_xor_sync(0xffffffffu, zz0, 1);  zz0 += __shfl_xor_sync(0xffffffffu, zz0, 2);
    zz1 += __shfl_xor_sync(0xffffffffu, zz1, 1);  zz1 += __shfl_xor_sync(0xffffffffu, zz1, 2);
    ws0 += __shfl_xor_sync(0xffffffffu, ws0, 1);  ws0 += __shfl_xor_sync(0xffffffffu, ws0, 2);
    ws1 += __shfl_xor_sync(0xffffffffu, ws1, 1);  ws1 += __shfl_xor_sync(0xffffffffu, ws1, 2);
    if (t == 0) {
        const size_t zb = (size_t)split * HEADS * SEQ + (size_t)h * SEQ;
        Zp[zb + rb + g]      = zz0;
        Zp[zb + rb + 8 + g]  = zz1;
        Wsp[zb + rb + g]     = ws0;
        Wsp[zb + rb + 8 + g] = ws1;
    }
    float* Ob = &Op[(size_t)split * SEQ * 512];
#pragma unroll
    for (int nf = 0; nf < 8; nf++) {
        const int col = h * 64 + nf * 8 + 2 * t;
        *reinterpret_cast<float2*>(&Ob[(size_t)(rb + g) * 512 + col]) =
            make_float2(o[nf][0], o[nf][1]);
        *reinterpret_cast<float2*>(&Ob[(size_t)(rb + 8 + g) * 512 + col]) =
            make_float2(o[nf][2], o[nf][3]);
    }
}

// ---------------- combine splits: out = 8*(sum O)/((sum z)*(sum ws)) -------
__global__ __launch_bounds__(256) void combine_kernel(float* __restrict__ out) {
    const int idx = blockIdx.x * 256 + threadIdx.x;   // 0 .. 4096*128-1
    const int n = idx >> 7;
    const int c = (idx & 127) * 4;
    const int h = c >> 6;
    const size_t zi = (size_t)h * SEQ + n;
    float4 acc = make_float4(0.f, 0.f, 0.f, 0.f);
    float z = 0.f, ws = 0.f;
#pragma unroll
    for (int s = 0; s < NSPLIT; s++) {
        const float4 a = *reinterpret_cast<const float4*>(
            &Op[(size_t)s * SEQ * 512 + (size_t)n * 512 + c]);
        acc.x += a.x; acc.y += a.y; acc.z += a.z; acc.w += a.w;
        z  += Zp[(size_t)s * HEADS * SEQ + zi];
        ws += Wsp[(size_t)s * HEADS * SEQ + zi];
    }
    const float inv = 8.f / (z * ws);
    float4 r;
    r.x = acc.x * inv;  r.y = acc.y * inv;
    r.z = acc.z * inv;  r.w = acc.w * inv;
    *reinterpret_cast<float4*>(&out[(size_t)n * 512 + c]) = r;
}

// ---------------- launch ---------------------------------------------------
extern "C" void kernel_launch(void* const* d_in, const int* in_sizes, int n_in,
                              void* d_out, int out_size) {
    const float* qk    = (const float*)d_in[0];   // (1, 4096, 768)
    const float* v_cls = (const float*)d_in[1];   // (1, 4096, 512)
    const float* masks = (const float*)d_in[2];   // (1, 4096, 4096)
    const float* W_qk  = (const float*)d_in[3];   // (768, 1536)
    const float* W_v   = (const float*)d_in[4];   // (512, 512)
    float* out = (float*)d_out;                   // (1, 4096, 512)

    cvt_inputs<<<(SEQ * 768 / 4 + 255) / 256, 256>>>(qk, v_cls);
    cvt_mask<<<(int)(((size_t)SEQ * SEQ / 8) / 256), 256>>>(masks);
    tr_cvt<<<dim3(1536 / 32, 768 / 32), 256>>>(W_qk, 768, 1536, 0);
    tr_cvt<<<dim3(512 / 32, 512 / 32), 256>>>(W_v, 512, 512, 1);

    cudaFuncSetAttribute(proj_kernel, cudaFuncAttributeMaxDynamicSharedMemorySize, PROJ_SMEM);
    proj_kernel<<<dim3(32, 32), 128, PROJ_SMEM>>>();

    cudaFuncSetAttribute(attn_kernel, cudaFuncAttributeMaxDynamicSharedMemorySize, ATTN_SMEM);
    attn_kernel<<<dim3(HEADS, SEQ / 64, NSPLIT), 128, ATTN_SMEM>>>();

    combine_kernel<<<(SEQ * 128) / 256, 256>>>(out);
}

// round 17
// speedup vs baseline: 1.3886x; 1.3886x over previous
#include <cuda_runtime.h>
#include <cuda_fp16.h>
#include <cstdint>

#define HEADS 8
#define SEQ   4096
#define DQK   96
#define DV    64
#define ATTN_SCALE 0.17677669529663689f   // (256/8)^-0.5
#define P_SCALE 0.015625f                 // 2^-6 (overflow guard for fp16 P)
#define NTILE_TOT 16384                   // 256 units x 64 key-tiles
#define NCTA  444                         // 3 CTAs/SM x 148 SMs

// ---------------- scratch (device globals: no allocation allowed) ----------
__device__ __half Qg[(size_t)HEADS * SEQ * DQK];   // [h][n][96] fp16, pre-scaled
__device__ __half Kg[(size_t)HEADS * SEQ * DQK];   // [h][n][96] fp16
__device__ __half Vtg[(size_t)HEADS * DV * SEQ];   // [h*64+d][n] fp16 (transposed V)
__device__ __half Ah[(size_t)SEQ * 768];           // qk fp16 row-major
__device__ __half Ch[(size_t)SEQ * 512];           // v_cls fp16 row-major
__device__ __half Wqt[(size_t)1536 * 768];         // W_qk^T fp16 [n][k]
__device__ __half Wvt[(size_t)512 * 512];          // W_v^T  fp16 [n][k]
__device__ __half Mh[(size_t)SEQ * SEQ];           // masks fp16
// persistent-schedule partial segments: unit u (=h*32+qb), slot 0..2
__device__ float OpS[(size_t)256 * 3 * 128 * 64];  // partial O
__device__ float ZpS[256 * 3 * 128];               // partial exp-sums
__device__ float WsS[256 * 3 * 128];               // partial mask row-sums

// ---------------- helpers --------------------------------------------------
__device__ __forceinline__ void cp16(uint32_t dst_smem, const void* src) {
    asm volatile("cp.async.cg.shared.global [%0], [%1], 16;" :: "r"(dst_smem), "l"(src));
}
#define CP_COMMIT() asm volatile("cp.async.commit_group;" ::)
#define CP_WAIT1()  asm volatile("cp.async.wait_group 1;" ::)
#define CP_WAIT0()  asm volatile("cp.async.wait_group 0;" ::)

__device__ __forceinline__ uint32_t s2u(const void* p) {
    return (uint32_t)__cvta_generic_to_shared(p);
}

// fp16: D(16x8,f32) += A(16x16,f16) * B(16x8,f16)
__device__ __forceinline__ void mma16(float c[4],
                                      uint32_t a0, uint32_t a1, uint32_t a2, uint32_t a3,
                                      uint32_t b0, uint32_t b1) {
    asm volatile(
        "mma.sync.aligned.m16n8k16.row.col.f32.f16.f16.f32 "
        "{%0,%1,%2,%3}, {%4,%5,%6,%7}, {%8,%9}, {%0,%1,%2,%3};"
        : "+f"(c[0]), "+f"(c[1]), "+f"(c[2]), "+f"(c[3])
        : "r"(a0), "r"(a1), "r"(a2), "r"(a3), "r"(b0), "r"(b1));
}

// ldmatrix x4: four 8x8 b16 matrices
__device__ __forceinline__ void ldsm4(uint32_t& x0, uint32_t& x1, uint32_t& x2, uint32_t& x3,
                                      uint32_t addr) {
    asm volatile("ldmatrix.sync.aligned.m8n8.x4.shared.b16 {%0,%1,%2,%3}, [%4];"
                 : "=r"(x0), "=r"(x1), "=r"(x2), "=r"(x3) : "r"(addr));
}

__device__ __forceinline__ uint32_t pack_h2(float lo, float hi) {
    __half2 h = __floats2half2_rn(lo, hi);
    return *reinterpret_cast<uint32_t*>(&h);
}

// static persistent schedule: CTA i owns tiles [tile_start(i), tile_start(i+1))
__host__ __device__ __forceinline__ int tile_start(int i) {
    return (int)(((long long)i * NTILE_TOT) / NCTA);
}

// ---------------- input conversion kernels ---------------------------------
__global__ __launch_bounds__(256) void cvt_inputs(const float* __restrict__ qk,
                                                  const float* __restrict__ v_cls) {
    const int i = blockIdx.x * 256 + threadIdx.x;          // float4 index
    if (i < (SEQ * 768) / 4) {
        float4 v = __ldg(reinterpret_cast<const float4*>(qk) + i);
        uint32_t* o = reinterpret_cast<uint32_t*>(Ah);
        o[i * 2]     = pack_h2(v.x, v.y);
        o[i * 2 + 1] = pack_h2(v.z, v.w);
    }
    if (i < (SEQ * 512) / 4) {
        float4 v = __ldg(reinterpret_cast<const float4*>(v_cls) + i);
        uint32_t* o = reinterpret_cast<uint32_t*>(Ch);
        o[i * 2]     = pack_h2(v.x, v.y);
        o[i * 2 + 1] = pack_h2(v.z, v.w);
    }
}

// masks f32 -> fp16 (8 floats / thread)
__global__ __launch_bounds__(256) void cvt_mask(const float* __restrict__ m) {
    const size_t i = (size_t)blockIdx.x * 256 + threadIdx.x;   // uint4 index
    const float4 a = __ldg(reinterpret_cast<const float4*>(m) + 2 * i);
    const float4 b = __ldg(reinterpret_cast<const float4*>(m) + 2 * i + 1);
    uint4 r;
    r.x = pack_h2(a.x, a.y); r.y = pack_h2(a.z, a.w);
    r.z = pack_h2(b.x, b.y); r.w = pack_h2(b.z, b.w);
    reinterpret_cast<uint4*>(Mh)[i] = r;
}

// W [K][N] f32 -> W^T [N][K] fp16, smem-tiled 32x32 transpose
__global__ __launch_bounds__(256) void tr_cvt(const float* __restrict__ in,
                                              int K, int N, int which) {
    __shared__ float tile[32][33];
    __half* out = which ? Wvt : Wqt;
    const int n0 = blockIdx.x * 32, k0 = blockIdx.y * 32;
    const int tx = threadIdx.x & 31, ty = threadIdx.x >> 5;   // 32 x 8
#pragma unroll
    for (int i = 0; i < 32; i += 8)
        tile[ty + i][tx] = __ldg(&in[(size_t)(k0 + ty + i) * N + n0 + tx]);
    __syncthreads();
#pragma unroll
    for (int i = 0; i < 32; i += 8)
        out[(size_t)(n0 + ty + i) * K + k0 + tx] = __float2half_rn(tile[tx][ty + i]);
}

// ---------------- fp16 projection GEMM (ldmatrix operands) -----------------
#define FA_STRIDE 20
#define FW_STRIDE 20
#define FSTAGE    (128 * FA_STRIDE + 64 * FW_STRIDE)   // 3840 words
#define PROJ_SMEM (2 * FSTAGE * 4)

__global__ __launch_bounds__(128) void proj_kernel() {
    extern __shared__ uint32_t smw[];

    const int  tid  = threadIdx.x;
    const int  w    = tid >> 5;
    const int  lane = tid & 31;
    const bool isV  = blockIdx.x >= 24;
    const uint32_t* A  = reinterpret_cast<const uint32_t*>(isV ? Ch : Ah);
    const uint32_t* Wt = reinterpret_cast<const uint32_t*>(isV ? Wvt : Wqt);
    const int  Kw   = isV ? 256 : 384;     // words (half2) per row
    const int  T    = isV ? 16 : 24;       // k-tiles of 32 halves
    const int  n0   = (isV ? (blockIdx.x - 24) : blockIdx.x) * 64;
    const int  m0   = blockIdx.y * 128;
    const uint32_t smem0 = s2u(smw);

    const int r_loc = lane & 7;
    const uint32_t afrag = (uint32_t)((r_loc + ((lane >> 3) & 1) * 8) * FA_STRIDE
                                      + ((lane >> 4) & 1) * 4) * 4u;
    const uint32_t bfrag = (uint32_t)(((((lane >> 4) & 1) * 8 + r_loc) * FW_STRIDE)
                                      + ((lane >> 3) & 1) * 4) * 4u;

    float acc[2][8][4];
#pragma unroll
    for (int r2 = 0; r2 < 2; r2++)
#pragma unroll
        for (int i = 0; i < 8; i++)
#pragma unroll
            for (int j = 0; j < 4; j++) acc[r2][i][j] = 0.f;

    auto issue = [&](int buf, int itk) {
        uint32_t Ab = smem0 + (uint32_t)(buf * FSTAGE) * 4u;
        uint32_t Wb = Ab + 128 * FA_STRIDE * 4u;
#pragma unroll
        for (int j = 0; j < 4; j++) {         // A tile: 128 rows x 16 words
            int idx = tid + j * 128;
            int r = idx >> 2, c = idx & 3;
            cp16(Ab + (uint32_t)(r * FA_STRIDE + c * 4) * 4u,
                 A + (size_t)(m0 + r) * Kw + itk * 16 + c * 4);
        }
#pragma unroll
        for (int j = 0; j < 2; j++) {         // W tile: 64 rows x 16 words
            int idx = tid + j * 128;
            int r = idx >> 2, c = idx & 3;
            cp16(Wb + (uint32_t)(r * FW_STRIDE + c * 4) * 4u,
                 Wt + (size_t)(n0 + r) * Kw + itk * 16 + c * 4);
        }
    };

    issue(0, 0); CP_COMMIT();

    for (int it = 0; it < T; it++) {
        if (it + 1 < T) { issue((it + 1) & 1, it + 1); CP_COMMIT(); CP_WAIT1(); }
        else            { CP_WAIT0(); }
        __syncthreads();

        const uint32_t Ab = smem0 + (uint32_t)((it & 1) * FSTAGE) * 4u;
        const uint32_t Wb = Ab + 128 * FA_STRIDE * 4u;

#pragma unroll
        for (int ks = 0; ks < 2; ks++) {
            uint32_t a[2][4];
#pragma unroll
            for (int r2 = 0; r2 < 2; r2++)
                ldsm4(a[r2][0], a[r2][1], a[r2][2], a[r2][3],
                      Ab + afrag + (uint32_t)(((w * 32 + r2 * 16) * FA_STRIDE + ks * 8)) * 4u);
#pragma unroll
            for (int nfp = 0; nfp < 4; nfp++) {
                uint32_t b0, b1, b2, b3;
                ldsm4(b0, b1, b2, b3,
                      Wb + bfrag + (uint32_t)((nfp * 2) * 8 * FW_STRIDE + ks * 8) * 4u);
                mma16(acc[0][nfp * 2],     a[0][0], a[0][1], a[0][2], a[0][3], b0, b1);
                mma16(acc[1][nfp * 2],     a[1][0], a[1][1], a[1][2], a[1][3], b0, b1);
                mma16(acc[0][nfp * 2 + 1], a[0][0], a[0][1], a[0][2], a[0][3], b2, b3);
                mma16(acc[1][nfp * 2 + 1], a[1][0], a[1][1], a[1][2], a[1][3], b2, b3);
            }
        }
        __syncthreads();
    }

    // epilogue -> fp16 scratch
    const int g = lane >> 2;
    const int t = lane & 3;
#pragma unroll
    for (int r2 = 0; r2 < 2; r2++)
#pragma unroll
        for (int nf = 0; nf < 8; nf++) {
            const int row = m0 + w * 32 + r2 * 16 + g;
            const int col = n0 + nf * 8 + 2 * t;
            if (!isV) {
                const bool isQ = col < 768;
                const int cc = isQ ? col : col - 768;
                const int h = cc / 96, d = cc - h * 96;
                const float sc = isQ ? ATTN_SCALE : 1.f;
                uint32_t* dst = reinterpret_cast<uint32_t*>(isQ ? Qg : Kg);
                dst[(((size_t)h * SEQ + row) * DQK + d) >> 1] =
                    pack_h2(acc[r2][nf][0] * sc, acc[r2][nf][1] * sc);
                dst[(((size_t)h * SEQ + row + 8) * DQK + d) >> 1] =
                    pack_h2(acc[r2][nf][2] * sc, acc[r2][nf][3] * sc);
            } else {
                Vtg[(size_t)col * SEQ + row]           = __float2half_rn(acc[r2][nf][0]);
                Vtg[(size_t)(col + 1) * SEQ + row]     = __float2half_rn(acc[r2][nf][1]);
                Vtg[(size_t)col * SEQ + row + 8]       = __float2half_rn(acc[r2][nf][2]);
                Vtg[(size_t)(col + 1) * SEQ + row + 8] = __float2half_rn(acc[r2][nf][3]);
            }
        }
}

// ---------------- fp16 flash attention: persistent 444-CTA schedule --------
// Global tile index tau in [0,16384): unit u = tau>>6 (h=u>>5, qb=u&31),
// key-tile kt = (tau&63)*64. CTA i owns [tile_start(i), tile_start(i+1))
// (~37 tiles, crosses <=1 unit boundary -> <=2 partial-segment flushes).
// Inner tile body identical to R14 (128-row CTA, su=2, ldmatrix, register-P).
#define BC 64
#define KW0 0
#define KW1 3328
#define VW0 6656
#define VW1 8960
#define ATTN_SMEM (11264 * 4)    // 45056 B -> 3 CTAs/SM

__global__ __launch_bounds__(128, 3) void attn_kernel() {
    extern __shared__ uint32_t smw[];

    const int tid  = threadIdx.x;
    const int w    = tid >> 5;
    const int lane = tid & 31;
    const int g    = lane >> 2;
    const int t    = lane & 3;
    const uint32_t smem0 = s2u(smw);
    const uint32_t* Mw = reinterpret_cast<const uint32_t*>(Mh);

    // ldmatrix per-lane address components (B operands)
    const int r_loc = lane & 7;
    const uint32_t kfrag = (uint32_t)((((lane >> 4) & 1) * 8 + r_loc) * 52
                                      + ((lane >> 3) & 1) * 4) * 4u;
    const uint32_t vfrag = (uint32_t)((((lane >> 4) & 1) * 8 + r_loc) * 36
                                      + ((lane >> 3) & 1) * 4) * 4u;

    const int ci   = blockIdx.x;
    int       tau  = tile_start(ci);
    const int tend = tile_start(ci + 1);

    // cp.async stage for global tile index tn (derives its own h/kt)
    auto issue = [&](int buf, int tn) {
        const int hn  = tn >> 11;               // (tn>>6)>>5
        const int ktn = (tn & 63) << 6;
        const __half* KhN = Kg  + (size_t)hn * SEQ * DQK;
        const __half* VhN = Vtg + (size_t)hn * DV * SEQ;
        uint32_t Kb = smem0 + (buf ? KW1 : KW0) * 4u;
        uint32_t Vb = smem0 + (buf ? VW1 : VW0) * 4u;
#pragma unroll
        for (int j = 0; j < 6; j++) {
            int idx = tid + j * 128;
            int r = idx / 12, c = idx % 12;
            cp16(Kb + (uint32_t)(r * 52 + c * 4) * 4u, KhN + (size_t)(ktn + r) * DQK + c * 8);
        }
#pragma unroll
        for (int j = 0; j < 4; j++) {
            int idx = tid + j * 128;
            int d0 = idx >> 3, c = idx & 7;
            cp16(Vb + (uint32_t)(d0 * 36 + c * 4) * 4u, VhN + (size_t)d0 * SEQ + ktn + c * 8);
        }
    };

    issue(tau & 1, tau); CP_COMMIT();

    while (tau < tend) {
        const int u  = tau >> 6;
        const int useg_end = min(tend, (u + 1) << 6);
        const int h  = u >> 5;
        const int qb = u & 31;
        const int rb = qb * 128 + w * 32;

        // per-unit state: Q fragments + mask row bases
        const uint32_t* Qw = reinterpret_cast<const uint32_t*>(Qg) + (size_t)h * SEQ * 48;
        uint32_t qa[2][6][4];
#pragma unroll
        for (int su = 0; su < 2; su++) {
            const int r = rb + su * 16 + g;
#pragma unroll
            for (int ks = 0; ks < 6; ks++) {
                qa[su][ks][0] = __ldg(&Qw[(size_t)r * 48 + ks * 8 + t]);
                qa[su][ks][1] = __ldg(&Qw[(size_t)(r + 8) * 48 + ks * 8 + t]);
                qa[su][ks][2] = __ldg(&Qw[(size_t)r * 48 + ks * 8 + t + 4]);
                qa[su][ks][3] = __ldg(&Qw[(size_t)(r + 8) * 48 + ks * 8 + t + 4]);
            }
        }
        size_t mrow[2][2];
#pragma unroll
        for (int su = 0; su < 2; su++) {
            mrow[su][0] = (size_t)(rb + su * 16 + g) * (SEQ / 2) + t;
            mrow[su][1] = (size_t)(rb + su * 16 + 8 + g) * (SEQ / 2) + t;
        }

        float o[2][8][4];
#pragma unroll
        for (int su = 0; su < 2; su++)
#pragma unroll
            for (int i = 0; i < 8; i++)
#pragma unroll
                for (int j = 0; j < 4; j++) o[su][i][j] = 0.f;
        float zz[4]  = {0.f, 0.f, 0.f, 0.f};
        float wss[4] = {0.f, 0.f, 0.f, 0.f};

        // ---- tiles of this segment ----
#pragma unroll 1
        for (; tau < useg_end; tau++) {
            const int buf = tau & 1;
            const int kt  = (tau & 63) << 6;

            CP_WAIT0();
            __syncthreads();
            if (tau + 1 < tend) { issue((tau + 1) & 1, tau + 1); CP_COMMIT(); }

            const uint32_t Kb = smem0 + (buf ? KW1 : KW0) * 4u;
            const uint32_t Vb = smem0 + (buf ? VW1 : VW0) * 4u;
            const int ktw = kt >> 1;

#pragma unroll
            for (int c2 = 0; c2 < 2; c2++) {
                // prefetch fp16 mask words (hidden under S-mma)
                uint32_t mk[2][2][4];
#pragma unroll
                for (int su = 0; su < 2; su++)
#pragma unroll
                    for (int nfl = 0; nfl < 4; nfl++) {
                        const int nf = c2 * 4 + nfl;
                        mk[su][0][nfl] = __ldg(&Mw[mrow[su][0] + ktw + nf * 4]);
                        mk[su][1][nfl] = __ldg(&Mw[mrow[su][1] + ktw + nf * 4]);
                    }

                // S = Q K^T for this 32-key chunk
                float s[2][4][4];
#pragma unroll
                for (int su = 0; su < 2; su++)
#pragma unroll
                    for (int i = 0; i < 4; i++)
#pragma unroll
                        for (int j = 0; j < 4; j++) s[su][i][j] = 0.f;
#pragma unroll
                for (int ks = 0; ks < 6; ks++) {
#pragma unroll
                    for (int nfp = 0; nfp < 2; nfp++) {
                        uint32_t b0, b1, b2, b3;
                        ldsm4(b0, b1, b2, b3,
                              Kb + kfrag + (uint32_t)((c2 * 4 + nfp * 2) * 416 + ks * 8) * 4u);
                        mma16(s[0][nfp * 2],     qa[0][ks][0], qa[0][ks][1], qa[0][ks][2], qa[0][ks][3], b0, b1);
                        mma16(s[1][nfp * 2],     qa[1][ks][0], qa[1][ks][1], qa[1][ks][2], qa[1][ks][3], b0, b1);
                        mma16(s[0][nfp * 2 + 1], qa[0][ks][0], qa[0][ks][1], qa[0][ks][2], qa[0][ks][3], b2, b3);
                        mma16(s[1][nfp * 2 + 1], qa[1][ks][0], qa[1][ks][1], qa[1][ks][2], qa[1][ks][3], b2, b3);
                    }
                }

                // softmax numerator * mask -> packed PV A-fragments
                uint32_t pa[2][2][4];
#pragma unroll
                for (int su = 0; su < 2; su++) {
#pragma unroll
                    for (int nfl = 0; nfl < 4; nfl++) {
                        float2 mv0 = __half22float2(*reinterpret_cast<__half2*>(&mk[su][0][nfl]));
                        float2 mv1 = __half22float2(*reinterpret_cast<__half2*>(&mk[su][1][nfl]));
                        float e00 = __expf(s[su][nfl][0]);
                        float e01 = __expf(s[su][nfl][1]);
                        float e10 = __expf(s[su][nfl][2]);
                        float e11 = __expf(s[su][nfl][3]);
                        zz[su * 2 + 0] += e00 + e01;  zz[su * 2 + 1] += e10 + e11;
                        wss[su * 2 + 0] += mv0.x + mv0.y;  wss[su * 2 + 1] += mv1.x + mv1.y;
                        pa[su][nfl >> 1][(nfl & 1) * 2 + 0] =
                            pack_h2(e00 * mv0.x * P_SCALE, e01 * mv0.y * P_SCALE);
                        pa[su][nfl >> 1][(nfl & 1) * 2 + 1] =
                            pack_h2(e10 * mv1.x * P_SCALE, e11 * mv1.y * P_SCALE);
                    }
                }

                // O += P~ @ V
#pragma unroll
                for (int kql = 0; kql < 2; kql++) {
                    const int kq = c2 * 2 + kql;
#pragma unroll
                    for (int nfp = 0; nfp < 4; nfp++) {
                        uint32_t b0, b1, b2, b3;
                        ldsm4(b0, b1, b2, b3,
                              Vb + vfrag + (uint32_t)((nfp * 2) * 288 + kq * 8) * 4u);
                        mma16(o[0][nfp * 2],     pa[0][kql][0], pa[0][kql][1], pa[0][kql][2], pa[0][kql][3], b0, b1);
                        mma16(o[1][nfp * 2],     pa[1][kql][0], pa[1][kql][1], pa[1][kql][2], pa[1][kql][3], b0, b1);
                        mma16(o[0][nfp * 2 + 1], pa[0][kql][0], pa[0][kql][1], pa[0][kql][2], pa[0][kql][3], b2, b3);
                        mma16(o[1][nfp * 2 + 1], pa[1][kql][0], pa[1][kql][1], pa[1][kql][2], pa[1][kql][3], b2, b3);
                    }
                }
            }
        }

        // ---- flush partial segment for unit u ----
#pragma unroll
        for (int r = 0; r < 4; r++) {
            zz[r]  += __shfl_xor_sync(0xffffffffu, zz[r], 1);
            zz[r]  += __shfl_xor_sync(0xffffffffu, zz[r], 2);
            wss[r] += __shfl_xor_sync(0xffffffffu, wss[r], 1);
            wss[r] += __shfl_xor_sync(0xffffffffu, wss[r], 2);
        }
        // slot = ci - (first CTA overlapping unit u); overlap: tile_start(j+1) > 64u
        int jlo = ci;
#pragma unroll
        for (int d = 2; d >= 0; d--) {
            const int j = ci - d;
            if (j >= 0 && tile_start(j + 1) > (u << 6)) { jlo = j; break; }
        }
        const int slot = ci - jlo;
        const size_t segbase = ((size_t)u * 3 + slot) * 128;

        if (t == 0) {
#pragma unroll
            for (int su = 0; su < 2; su++) {
                ZpS[segbase + w * 32 + su * 16 + g]      = zz[su * 2 + 0];
                ZpS[segbase + w * 32 + su * 16 + 8 + g]  = zz[su * 2 + 1];
                WsS[segbase + w * 32 + su * 16 + g]      = wss[su * 2 + 0];
                WsS[segbase + w * 32 + su * 16 + 8 + g]  = wss[su * 2 + 1];
            }
        }
#pragma unroll
        for (int su = 0; su < 2; su++) {
            const int r0 = w * 32 + su * 16 + g;
#pragma unroll
            for (int nf = 0; nf < 8; nf++) {
                const int col = nf * 8 + 2 * t;
                *reinterpret_cast<float2*>(&OpS[(segbase + r0) * 64 + col]) =
                    make_float2(o[su][nf][0], o[su][nf][1]);
                *reinterpret_cast<float2*>(&OpS[(segbase + r0 + 8) * 64 + col]) =
                    make_float2(o[su][nf][2], o[su][nf][3]);
            }
        }
    }
}

// ---------------- combine segments: out = 8*(sum O)/((sum z)*(sum ws)) -----
__global__ __launch_bounds__(256) void combine_kernel(float* __restrict__ out) {
    const int idx = blockIdx.x * 256 + threadIdx.x;   // 0 .. 4096*128-1
    const int n  = idx >> 7;
    const int c4 = (idx & 127) * 4;
    const int h  = c4 >> 6;
    const int u  = h * 32 + (n >> 7);
    const int r  = n & 127;
    const int lc = c4 & 63;

    // find CTAs overlapping unit u (same static schedule as attn_kernel)
    const int base = u << 6, nxt = base + 64;
    int j = (int)(((long long)base * NCTA) / NTILE_TOT);
    j = (j > 2) ? (j - 2) : 0;
    while (tile_start(j + 1) <= base) j++;

    float4 acc = make_float4(0.f, 0.f, 0.f, 0.f);
    float z = 0.f, ws = 0.f;
    int s = 0;
    while (j < NCTA && tile_start(j) < nxt) {
        const size_t segbase = ((size_t)u * 3 + s) * 128;
        const float4 a = *reinterpret_cast<const float4*>(&OpS[(segbase + r) * 64 + lc]);
        acc.x += a.x; acc.y += a.y; acc.z += a.z; acc.w += a.w;
        z  += ZpS[segbase + r];
        ws += WsS[segbase + r];
        s++; j++;
    }
    const float inv = 8.f / (z * ws);
    float4 o;
    o.x = acc.x * inv;  o.y = acc.y * inv;
    o.z = acc.z * inv;  o.w = acc.w * inv;
    *reinterpret_cast<float4*>(&out[(size_t)n * 512 + c4]) = o;
}

// ---------------- launch ---------------------------------------------------
extern "C" void kernel_launch(void* const* d_in, const int* in_sizes, int n_in,
                              void* d_out, int out_size) {
    const float* qk    = (const float*)d_in[0];   // (1, 4096, 768)
    const float* v_cls = (const float*)d_in[1];   // (1, 4096, 512)
    const float* masks = (const float*)d_in[2];   // (1, 4096, 4096)
    const float* W_qk  = (const float*)d_in[3];   // (768, 1536)
    const float* W_v   = (const float*)d_in[4];   // (512, 512)
    float* out = (float*)d_out;                   // (1, 4096, 512)

    cvt_inputs<<<(SEQ * 768 / 4 + 255) / 256, 256>>>(qk, v_cls);
    cvt_mask<<<(int)(((size_t)SEQ * SEQ / 8) / 256), 256>>>(masks);
    tr_cvt<<<dim3(1536 / 32, 768 / 32), 256>>>(W_qk, 768, 1536, 0);
    tr_cvt<<<dim3(512 / 32, 512 / 32), 256>>>(W_v, 512, 512, 1);

    cudaFuncSetAttribute(proj_kernel, cudaFuncAttributeMaxDynamicSharedMemorySize, PROJ_SMEM);
    proj_kernel<<<dim3(32, 32), 128, PROJ_SMEM>>>();

    cudaFuncSetAttribute(attn_kernel, cudaFuncAttributeMaxDynamicSharedMemorySize, ATTN_SMEM);
    attn_kernel<<<NCTA, 128, ATTN_SMEM>>>();

    combine_kernel<<<(SEQ * 128) / 256, 256>>>(out);
}